// round 1
// baseline (speedup 1.0000x reference)
#include <cuda_runtime.h>
#include <math.h>

// ---------------- problem constants ----------------
#define BATCH 4096
#define LSEQ  28
#define VOCAB 32000
#define DIM   300
#define EFW   (DIM*LSEQ)      // 8400
#define L1o   13
#define C1    300
#define L2o   5
#define C2    600
#define C3    100
#define NPAIRS 8386560        // 4096*4095/2
#define HOUT  (BATCH*C3)      // 409600

// ---------------- scratch (__device__ globals; no allocation allowed) ----------------
__device__ float g_Ef[(size_t)BATCH*EFW];          // x_embedded, [B][D*L] = [B][ci*28+l]
__device__ float g_h1[(size_t)BATCH*C1*L1o];
__device__ float g_h2[(size_t)BATCH*C2*L2o];
__device__ float g_final[BATCH*C3];
__device__ float g_Fn[BATCH*112];                  // normalized final, padded K 100->112
__device__ float g_scales[VOCAB];
__device__ float g_w1t[1500*C1];                   // [ci*5+k][co]
__device__ float g_w2t[1500*C2];
__device__ float g_w3t[3000*C3];
__device__ float g_mean1[C1], g_istd1[C1];
__device__ float g_mean2[C2], g_istd2[C2];

// ---------------- embedding renorm scales ----------------
__global__ void k_scales(const float* __restrict__ emb) {
    int warp = (blockIdx.x * blockDim.x + threadIdx.x) >> 5;
    int lane = threadIdx.x & 31;
    if (warp >= VOCAB) return;
    const float* row = emb + (size_t)warp * DIM;
    float s = 0.f;
    for (int d = lane; d < DIM; d += 32) { float v = row[d]; s += v * v; }
    #pragma unroll
    for (int o = 16; o; o >>= 1) s += __shfl_xor_sync(0xffffffffu, s, o);
    if (lane == 0) g_scales[warp] = fminf(1.f, 1.f / (sqrtf(s) + 1e-7f));
}

// ---------------- gather + transpose to [B][D][L] ----------------
__global__ void k_gather(const int* __restrict__ x, const float* __restrict__ emb) {
    __shared__ float sm[EFW];
    __shared__ int   tok[LSEQ];
    __shared__ float sc[LSEQ];
    int b = blockIdx.x, t = threadIdx.x;
    // detect int64 vs int32 index buffer: int64 little-endian -> odd words are 0
    bool is64 = (x[1] == 0 && x[3] == 0 && x[5] == 0 && x[7] == 0);
    if (t < LSEQ) {
        int v = is64 ? x[(b * LSEQ + t) * 2] : x[b * LSEQ + t];
        tok[t] = v;
        sc[t]  = g_scales[v];
    }
    __syncthreads();
    for (int i = t; i < EFW; i += blockDim.x) {
        int l = i / DIM, d = i - l * DIM;
        sm[d * LSEQ + l] = emb[(size_t)tok[l] * DIM + d] * sc[l];
    }
    __syncthreads();
    float* dst = g_Ef + (size_t)b * EFW;
    for (int i = t; i < EFW; i += blockDim.x) dst[i] = sm[i];
}

// ---------------- weight transposes: w[co][ci][k] -> wt[ci*5+k][co] ----------------
__global__ void k_transpose(const float* __restrict__ w1,
                            const float* __restrict__ w2,
                            const float* __restrict__ w3) {
    int idx = blockIdx.x * blockDim.x + threadIdx.x;
    const int n1 = C1 * 1500, n2 = C2 * 1500, n3 = C3 * 3000;
    if (idx < n1) { int co = idx / 1500, cik = idx - co * 1500; g_w1t[cik * C1 + co] = w1[idx]; return; }
    idx -= n1;
    if (idx < n2) { int co = idx / 1500, cik = idx - co * 1500; g_w2t[cik * C2 + co] = w2[idx]; return; }
    idx -= n2;
    if (idx < n3) { int co = idx / 3000, cik = idx - co * 3000; g_w3t[cik * C3 + co] = w3[idx]; }
}

// ---------------- conv1: 300ch,K5,s2,p1  (2 batches per block) ----------------
__global__ __launch_bounds__(320)
void k_conv1(const float* __restrict__ b1) {
    extern __shared__ float xs[];   // [2][300][29], slot 0 = left zero-pad
    int t = threadIdx.x;
    int b0 = blockIdx.x * 2;
    for (int i = t; i < 2 * EFW; i += 320) {
        int bb = i / EFW, r = i - bb * EFW;
        int ci = r / LSEQ, l = r - ci * LSEQ;
        xs[bb * 8700 + ci * 29 + 1 + l] = g_Ef[(size_t)(b0 + bb) * EFW + r];
    }
    for (int i = t; i < 600; i += 320) {
        int bb = i / 300, ci = i - bb * 300;
        xs[bb * 8700 + ci * 29] = 0.f;
    }
    __syncthreads();
    if (t >= C1) return;
    int co = t;
    float bias = b1[co];
    float a0[L1o], a1[L1o];
    #pragma unroll
    for (int l = 0; l < L1o; l++) { a0[l] = bias; a1[l] = bias; }
    for (int ci = 0; ci < C1; ci++) {
        float v0[29], v1[29];
        const float* p0 = xs + ci * 29;
        const float* p1 = xs + 8700 + ci * 29;
        #pragma unroll
        for (int j = 0; j < 29; j++) { v0[j] = p0[j]; v1[j] = p1[j]; }
        #pragma unroll
        for (int k = 0; k < 5; k++) {
            float w = g_w1t[(ci * 5 + k) * C1 + co];
            #pragma unroll
            for (int l = 0; l < L1o; l++) {
                a0[l] += w * v0[2 * l + k];
                a1[l] += w * v1[2 * l + k];
            }
        }
    }
    float* o0 = g_h1 + ((size_t)(b0 + 0) * C1 + co) * L1o;
    float* o1 = g_h1 + ((size_t)(b0 + 1) * C1 + co) * L1o;
    #pragma unroll
    for (int l = 0; l < L1o; l++) { o0[l] = a0[l]; o1[l] = a1[l]; }
}

// ---------------- BN stats (deterministic per-channel block reduction) ----------------
__global__ void k_bnstats(int which) {
    int C = (which == 1) ? C1 : C2;
    int L = (which == 1) ? L1o : L2o;
    const float* h = (which == 1) ? g_h1 : g_h2;
    int c = blockIdx.x, t = threadIdx.x;
    const int N = BATCH * L;
    float s = 0.f, s2 = 0.f;
    for (int idx = t; idx < N; idx += blockDim.x) {
        int b = idx / L, l = idx - b * L;
        float v = h[((size_t)b * C + c) * L + l];
        s += v; s2 += v * v;
    }
    #pragma unroll
    for (int o = 16; o; o >>= 1) {
        s  += __shfl_xor_sync(0xffffffffu, s, o);
        s2 += __shfl_xor_sync(0xffffffffu, s2, o);
    }
    __shared__ float sh[64];
    int w = t >> 5, lane = t & 31;
    if (lane == 0) { sh[w] = s; sh[32 + w] = s2; }
    __syncthreads();
    if (t == 0) {
        float S = 0.f, S2 = 0.f;
        int nw = blockDim.x >> 5;
        for (int i = 0; i < nw; i++) { S += sh[i]; S2 += sh[32 + i]; }
        float m = S / N;
        float var = S2 / N - m * m;
        if (which == 1) { g_mean1[c] = m; g_istd1[c] = rsqrtf(var + 1e-5f); }
        else            { g_mean2[c] = m; g_istd2[c] = rsqrtf(var + 1e-5f); }
    }
}

__global__ void k_bnapply(const float* __restrict__ gamma, const float* __restrict__ beta, int which) {
    int C = (which == 1) ? C1 : C2;
    int L = (which == 1) ? L1o : L2o;
    float* h = (which == 1) ? g_h1 : g_h2;
    const float* mean = (which == 1) ? g_mean1 : g_mean2;
    const float* istd = (which == 1) ? g_istd1 : g_istd2;
    size_t total = (size_t)BATCH * C * L;
    size_t stride = (size_t)gridDim.x * blockDim.x;
    for (size_t idx = (size_t)blockIdx.x * blockDim.x + threadIdx.x; idx < total; idx += stride) {
        int c = (int)((idx / L) % C);
        float v = h[idx];
        v = (v - mean[c]) * istd[c] * gamma[c] + beta[c];
        h[idx] = fmaxf(v, 0.f);
    }
}

// ---------------- conv2: 300->600, K5, s2, p0  (4 batches per block, 608 threads) ----------------
__global__ __launch_bounds__(608)
void k_conv2(const float* __restrict__ b2) {
    extern __shared__ float xs[];   // [4][300*13]
    int t = threadIdx.x;
    int b0 = blockIdx.x * 4;
    for (int i = t; i < 4 * 3900; i += 608) xs[i] = g_h1[(size_t)b0 * 3900 + i];
    __syncthreads();
    if (t >= C2) return;
    int co = t;
    float bias = b2[co];
    float acc[4][L2o];
    #pragma unroll
    for (int bb = 0; bb < 4; bb++)
        #pragma unroll
        for (int l = 0; l < L2o; l++) acc[bb][l] = bias;
    for (int ci = 0; ci < 300; ci++) {
        float v[4][13];
        #pragma unroll
        for (int bb = 0; bb < 4; bb++)
            #pragma unroll
            for (int j = 0; j < 13; j++) v[bb][j] = xs[bb * 3900 + ci * 13 + j];
        #pragma unroll
        for (int k = 0; k < 5; k++) {
            float w = g_w2t[(ci * 5 + k) * C2 + co];
            #pragma unroll
            for (int bb = 0; bb < 4; bb++)
                #pragma unroll
                for (int l = 0; l < L2o; l++) acc[bb][l] += w * v[bb][2 * l + k];
        }
    }
    #pragma unroll
    for (int bb = 0; bb < 4; bb++) {
        float* o = g_h2 + ((size_t)(b0 + bb) * C2 + co) * L2o;
        #pragma unroll
        for (int l = 0; l < L2o; l++) o[l] = acc[bb][l];
    }
}

// ---------------- conv3: 600->100, K5, s2, p0, tanh  (4 batches per block) ----------------
__global__ __launch_bounds__(512)
void k_conv3(const float* __restrict__ b3, float* __restrict__ out_h) {
    __shared__ float xs[12000];     // 4 * 3000
    int t = threadIdx.x;
    int b0 = blockIdx.x * 4;
    for (int i = t; i < 12000; i += 512) xs[i] = g_h2[(size_t)b0 * 3000 + i];
    __syncthreads();
    if (t >= 400) return;
    int bb = t / 100, co = t - bb * 100;
    const float* xr = xs + bb * 3000;
    float acc = b3[co];
    #pragma unroll 8
    for (int j = 0; j < 3000; j++) acc += g_w3t[j * C3 + co] * xr[j];
    float v = tanhf(acc);
    int b = b0 + bb;
    out_h[b * C3 + co]   = v;
    g_final[b * C3 + co] = v;
}

// ---------------- row-normalize final -> Fn (padded to 112) ----------------
__global__ void k_norm() {
    int gw = (blockIdx.x * blockDim.x + threadIdx.x) >> 5;
    int lane = threadIdx.x & 31;
    if (gw >= BATCH) return;
    const float* f = g_final + gw * C3;
    float s = 0.f;
    for (int c = lane; c < C3; c += 32) { float v = f[c]; s += v * v; }
    #pragma unroll
    for (int o = 16; o; o >>= 1) s += __shfl_xor_sync(0xffffffffu, s, o);
    float n = sqrtf(s);
    float* o = g_Fn + gw * 112;
    for (int c = lane; c < C3; c += 32) o[c] = f[c] / n;
    if (lane < 12) o[100 + lane] = 0.f;
}

// ---------------- symmetric Gram (X * X^T), upper-triangle packed output ----------------
// 128x128 tile, 256 threads, 8x8 micro-tile, Kc=16. Only tiles tj >= ti.
__global__ __launch_bounds__(256, 2)
void k_gram(int src, int kIters, float* __restrict__ out) {
    const float* X; int ld;
    if (src == 0) { X = g_Ef; ld = EFW; } else { X = g_Fn; ld = 112; }

    // block -> (ti, tj) with tj >= ti, 32 tiles per dim -> 528 blocks
    int p = blockIdx.x;
    int ti = 0, rem = 32;
    while (p >= rem) { p -= rem; rem--; ti++; }
    int tj = ti + p;
    const int i0 = ti * 128, j0 = tj * 128;

    __shared__ float As[16][132];
    __shared__ float Bs[16][132];

    int t  = threadIdx.x;
    int tx = t & 15, ty = t >> 4;

    float c[8][8];
    #pragma unroll
    for (int u = 0; u < 8; u++)
        #pragma unroll
        for (int v = 0; v < 8; v++) c[u][v] = 0.f;

    const float* Abase = X + (size_t)i0 * ld;
    const float* Bbase = X + (size_t)j0 * ld;
    int kMax = kIters * 16;

    for (int kc = 0; kc < kMax; kc += 16) {
        #pragma unroll
        for (int q = 0; q < 2; q++) {
            int idx = t + q * 256;
            int row = idx >> 2;
            int kq  = (idx & 3) * 4;
            float4 a = *(const float4*)(Abase + (size_t)row * ld + kc + kq);
            float4 b = *(const float4*)(Bbase + (size_t)row * ld + kc + kq);
            As[kq + 0][row] = a.x; As[kq + 1][row] = a.y; As[kq + 2][row] = a.z; As[kq + 3][row] = a.w;
            Bs[kq + 0][row] = b.x; Bs[kq + 1][row] = b.y; Bs[kq + 2][row] = b.z; Bs[kq + 3][row] = b.w;
        }
        __syncthreads();
        #pragma unroll
        for (int kk = 0; kk < 16; kk++) {
            float a[8], b[8];
            #pragma unroll
            for (int u = 0; u < 8; u++) a[u] = As[kk][ty * 8 + u];
            #pragma unroll
            for (int v = 0; v < 8; v++) b[v] = Bs[kk][tx * 8 + v];
            #pragma unroll
            for (int u = 0; u < 8; u++)
                #pragma unroll
                for (int v = 0; v < 8; v++) c[u][v] += a[u] * b[v];
        }
        __syncthreads();
    }

    // packed triu write: idx(i,j) = i*(8191-i)/2 + (j-i-1)
    #pragma unroll
    for (int u = 0; u < 8; u++) {
        int i = i0 + ty * 8 + u;
        int base = i * (8191 - i) / 2 - i - 1;
        #pragma unroll
        for (int v = 0; v < 8; v++) {
            int j = j0 + tx * 8 + v;
            if (j > i) out[base + j] = c[u][v];
        }
    }
}

// ---------------- launch ----------------
extern "C" void kernel_launch(void* const* d_in, const int* in_sizes, int n_in,
                              void* d_out, int out_size) {
    const int*   x   = (const int*)  d_in[0];
    const float* emb = (const float*)d_in[1];
    const float* w1  = (const float*)d_in[2];
    const float* b1  = (const float*)d_in[3];
    const float* w2  = (const float*)d_in[4];
    const float* b2  = (const float*)d_in[5];
    const float* w3  = (const float*)d_in[6];
    const float* b3  = (const float*)d_in[7];
    const float* g1  = (const float*)d_in[8];
    const float* be1 = (const float*)d_in[9];
    const float* g2  = (const float*)d_in[10];
    const float* be2 = (const float*)d_in[11];
    float* out = (float*)d_out;

    cudaFuncSetAttribute(k_conv1, cudaFuncAttributeMaxDynamicSharedMemorySize, 2 * 8700 * 4);
    cudaFuncSetAttribute(k_conv2, cudaFuncAttributeMaxDynamicSharedMemorySize, 4 * 3900 * 4);

    k_scales<<<(VOCAB * 32 + 255) / 256, 256>>>(emb);
    k_gather<<<BATCH, 256>>>(x, emb);
    k_transpose<<<(1650000 + 255) / 256, 256>>>(w1, w2, w3);

    k_conv1<<<BATCH / 2, 320, 2 * 8700 * 4>>>(b1);
    k_bnstats<<<C1, 256>>>(1);
    k_bnapply<<<2048, 256>>>(g1, be1, 1);

    k_conv2<<<BATCH / 4, 608, 4 * 3900 * 4>>>(b2);
    k_bnstats<<<C2, 256>>>(2);
    k_bnapply<<<2048, 256>>>(g2, be2, 2);

    k_conv3<<<BATCH / 4, 512>>>(b3, out);
    k_norm<<<BATCH * 32 / 256, 256>>>();

    k_gram<<<528, 256>>>(0, EFW / 16, out + HOUT);            // input_pws
    k_gram<<<528, 256>>>(1, 112 / 16, out + HOUT + NPAIRS);   // hidden_pws
}

// round 2
// speedup vs baseline: 1.4742x; 1.4742x over previous
#include <cuda_runtime.h>
#include <cuda_bf16.h>
#include <math.h>

// ---------------- problem constants ----------------
#define BATCH 4096
#define LSEQ  28
#define VOCAB 32000
#define DIM   300
#define EFW   (DIM*LSEQ)      // 8400
#define KPAD_E 8448           // 8400 padded to multiple of 32 (and 256)
#define KPAD_F 128            // 100 padded
#define L1o   13
#define C1    300
#define L2o   5
#define C2    600
#define C3    100
#define NPAIRS 8386560        // 4096*4095/2
#define HOUT  (BATCH*C3)      // 409600

// ---------------- scratch ----------------
__device__ float g_Ef[(size_t)BATCH*EFW];
__device__ __nv_bfloat16 g_Ehi[(size_t)BATCH*KPAD_E];
__device__ __nv_bfloat16 g_Elo[(size_t)BATCH*KPAD_E];
__device__ float g_h1[(size_t)BATCH*C1*L1o];
__device__ float g_h2[(size_t)BATCH*C2*L2o];
__device__ float g_final[BATCH*C3];
__device__ __nv_bfloat16 g_Fnh[BATCH*KPAD_F];
__device__ __nv_bfloat16 g_Fnl[BATCH*KPAD_F];
__device__ float g_scales[VOCAB];
__device__ float g_w1t[1500*C1];
__device__ float g_w2t[1500*C2];
__device__ float g_w3t[3000*C3];
__device__ float g_mean1[C1], g_istd1[C1];
__device__ float g_mean2[C2], g_istd2[C2];

// ---------------- embedding renorm scales ----------------
__global__ void k_scales(const float* __restrict__ emb) {
    int warp = (blockIdx.x * blockDim.x + threadIdx.x) >> 5;
    int lane = threadIdx.x & 31;
    if (warp >= VOCAB) return;
    const float* row = emb + (size_t)warp * DIM;
    float s = 0.f;
    for (int d = lane; d < DIM; d += 32) { float v = row[d]; s += v * v; }
    #pragma unroll
    for (int o = 16; o; o >>= 1) s += __shfl_xor_sync(0xffffffffu, s, o);
    if (lane == 0) g_scales[warp] = fminf(1.f, 1.f / (sqrtf(s) + 1e-7f));
}

// ---------------- gather + transpose + bf16 split ----------------
__global__ void k_gather(const int* __restrict__ x, const float* __restrict__ emb) {
    __shared__ float sm[EFW];
    __shared__ int   tok[LSEQ];
    __shared__ float sc[LSEQ];
    int b = blockIdx.x, t = threadIdx.x;
    bool is64 = (x[1] == 0 && x[3] == 0 && x[5] == 0 && x[7] == 0);
    if (t < LSEQ) {
        int v = is64 ? x[(b * LSEQ + t) * 2] : x[b * LSEQ + t];
        tok[t] = v;
        sc[t]  = g_scales[v];
    }
    __syncthreads();
    for (int i = t; i < EFW; i += blockDim.x) {
        int l = i / DIM, d = i - l * DIM;
        sm[d * LSEQ + l] = emb[(size_t)tok[l] * DIM + d] * sc[l];
    }
    __syncthreads();
    float* dstF = g_Ef + (size_t)b * EFW;
    __nv_bfloat16* dH = g_Ehi + (size_t)b * KPAD_E;
    __nv_bfloat16* dL = g_Elo + (size_t)b * KPAD_E;
    for (int i = t; i < EFW; i += blockDim.x) {
        float v = sm[i];
        dstF[i] = v;
        __nv_bfloat16 h = __float2bfloat16(v);
        dH[i] = h;
        dL[i] = __float2bfloat16(v - __bfloat162float(h));
    }
    for (int i = EFW + t; i < KPAD_E; i += blockDim.x) {
        dH[i] = __float2bfloat16(0.f);
        dL[i] = __float2bfloat16(0.f);
    }
}

// ---------------- weight transposes ----------------
__global__ void k_transpose(const float* __restrict__ w1,
                            const float* __restrict__ w2,
                            const float* __restrict__ w3) {
    int idx = blockIdx.x * blockDim.x + threadIdx.x;
    const int n1 = C1 * 1500, n2 = C2 * 1500, n3 = C3 * 3000;
    if (idx < n1) { int co = idx / 1500, cik = idx - co * 1500; g_w1t[cik * C1 + co] = w1[idx]; return; }
    idx -= n1;
    if (idx < n2) { int co = idx / 1500, cik = idx - co * 1500; g_w2t[cik * C2 + co] = w2[idx]; return; }
    idx -= n2;
    if (idx < n3) { int co = idx / 3000, cik = idx - co * 3000; g_w3t[cik * C3 + co] = w3[idx]; }
}

// ---------------- conv1: 300ch,K5,s2,p1 (2 batches/block, float4 smem rows) ----------------
__global__ __launch_bounds__(320)
void k_conv1(const float* __restrict__ b1) {
    extern __shared__ float xs[];   // [2][300][32]; col 0 = left pad, cols 29..31 zero
    int t = threadIdx.x;
    int b0 = blockIdx.x * 2;
    for (int i = t; i < 2 * 9600; i += 320) xs[i] = 0.f;
    __syncthreads();
    for (int i = t; i < 2 * EFW; i += 320) {
        int bb = i / EFW, r = i - bb * EFW;
        int ci = r / LSEQ, l = r - ci * LSEQ;
        xs[bb * 9600 + ci * 32 + 1 + l] = g_Ef[(size_t)(b0 + bb) * EFW + r];
    }
    __syncthreads();
    if (t >= C1) return;
    int co = t;
    float bias = b1[co];
    float a0[L1o], a1[L1o];
    #pragma unroll
    for (int l = 0; l < L1o; l++) { a0[l] = bias; a1[l] = bias; }
    const float4* x40 = (const float4*)xs;
    const float4* x41 = (const float4*)(xs + 9600);
    for (int ci = 0; ci < C1; ci++) {
        float w[5];
        #pragma unroll
        for (int k = 0; k < 5; k++) w[k] = g_w1t[(ci * 5 + k) * C1 + co];
        float v[32];
        #pragma unroll
        for (int q = 0; q < 8; q++) *(float4*)(v + 4 * q) = x40[ci * 8 + q];
        #pragma unroll
        for (int k = 0; k < 5; k++)
            #pragma unroll
            for (int l = 0; l < L1o; l++) a0[l] += w[k] * v[2 * l + k];
        #pragma unroll
        for (int q = 0; q < 8; q++) *(float4*)(v + 4 * q) = x41[ci * 8 + q];
        #pragma unroll
        for (int k = 0; k < 5; k++)
            #pragma unroll
            for (int l = 0; l < L1o; l++) a1[l] += w[k] * v[2 * l + k];
    }
    float* o0 = g_h1 + ((size_t)(b0 + 0) * C1 + co) * L1o;
    float* o1 = g_h1 + ((size_t)(b0 + 1) * C1 + co) * L1o;
    #pragma unroll
    for (int l = 0; l < L1o; l++) { o0[l] = a0[l]; o1[l] = a1[l]; }
}

// ---------------- BN stats ----------------
__global__ void k_bnstats(int which) {
    int C = (which == 1) ? C1 : C2;
    int L = (which == 1) ? L1o : L2o;
    const float* h = (which == 1) ? g_h1 : g_h2;
    int c = blockIdx.x, t = threadIdx.x;
    const int N = BATCH * L;
    float s = 0.f, s2 = 0.f;
    for (int idx = t; idx < N; idx += blockDim.x) {
        int b = idx / L, l = idx - b * L;
        float v = h[((size_t)b * C + c) * L + l];
        s += v; s2 += v * v;
    }
    #pragma unroll
    for (int o = 16; o; o >>= 1) {
        s  += __shfl_xor_sync(0xffffffffu, s, o);
        s2 += __shfl_xor_sync(0xffffffffu, s2, o);
    }
    __shared__ float sh[64];
    int w = t >> 5, lane = t & 31;
    if (lane == 0) { sh[w] = s; sh[32 + w] = s2; }
    __syncthreads();
    if (t == 0) {
        float S = 0.f, S2 = 0.f;
        int nw = blockDim.x >> 5;
        for (int i = 0; i < nw; i++) { S += sh[i]; S2 += sh[32 + i]; }
        float m = S / N;
        float var = S2 / N - m * m;
        if (which == 1) { g_mean1[c] = m; g_istd1[c] = rsqrtf(var + 1e-5f); }
        else            { g_mean2[c] = m; g_istd2[c] = rsqrtf(var + 1e-5f); }
    }
}

__global__ void k_bnapply(const float* __restrict__ gamma, const float* __restrict__ beta, int which) {
    int C = (which == 1) ? C1 : C2;
    int L = (which == 1) ? L1o : L2o;
    float* h = (which == 1) ? g_h1 : g_h2;
    const float* mean = (which == 1) ? g_mean1 : g_mean2;
    const float* istd = (which == 1) ? g_istd1 : g_istd2;
    size_t total = (size_t)BATCH * C * L;
    size_t stride = (size_t)gridDim.x * blockDim.x;
    for (size_t idx = (size_t)blockIdx.x * blockDim.x + threadIdx.x; idx < total; idx += stride) {
        int c = (int)((idx / L) % C);
        float v = h[idx];
        v = (v - mean[c]) * istd[c] * gamma[c] + beta[c];
        h[idx] = fmaxf(v, 0.f);
    }
}

// ---------------- conv2: 300->600, K5, s2, p0 (4 batches/block, padded rows) ----------------
__global__ __launch_bounds__(608)
void k_conv2(const float* __restrict__ b2) {
    extern __shared__ float xs[];   // [4][300][16], cols 13..15 zero
    int t = threadIdx.x;
    int b0 = blockIdx.x * 4;
    for (int i = t; i < 4 * 4800; i += 608) xs[i] = 0.f;
    __syncthreads();
    for (int i = t; i < 4 * 3900; i += 608) {
        int bb = i / 3900, r = i - bb * 3900;
        int ci = r / 13, l = r - ci * 13;
        xs[bb * 4800 + ci * 16 + l] = g_h1[(size_t)b0 * 3900 + i];
    }
    __syncthreads();
    if (t >= C2) return;
    int co = t;
    float bias = b2[co];
    float acc[4][L2o];
    #pragma unroll
    for (int bb = 0; bb < 4; bb++)
        #pragma unroll
        for (int l = 0; l < L2o; l++) acc[bb][l] = bias;
    const float4* x4 = (const float4*)xs;
    for (int ci = 0; ci < 300; ci++) {
        float w[5];
        #pragma unroll
        for (int k = 0; k < 5; k++) w[k] = g_w2t[(ci * 5 + k) * C2 + co];
        #pragma unroll
        for (int bb = 0; bb < 4; bb++) {
            float v[16];
            #pragma unroll
            for (int q = 0; q < 4; q++) *(float4*)(v + 4 * q) = x4[bb * 1200 + ci * 4 + q];
            #pragma unroll
            for (int k = 0; k < 5; k++)
                #pragma unroll
                for (int l = 0; l < L2o; l++) acc[bb][l] += w[k] * v[2 * l + k];
        }
    }
    #pragma unroll
    for (int bb = 0; bb < 4; bb++) {
        float* o = g_h2 + ((size_t)(b0 + bb) * C2 + co) * L2o;
        #pragma unroll
        for (int l = 0; l < L2o; l++) o[l] = acc[bb][l];
    }
}

// ---------------- conv3: 600->100, K5, s2, p0, tanh ----------------
__global__ __launch_bounds__(512)
void k_conv3(const float* __restrict__ b3, float* __restrict__ out_h) {
    __shared__ float xs[12000];
    int t = threadIdx.x;
    int b0 = blockIdx.x * 4;
    for (int i = t; i < 12000; i += 512) xs[i] = g_h2[(size_t)b0 * 3000 + i];
    __syncthreads();
    if (t >= 400) return;
    int bb = t / 100, co = t - bb * 100;
    const float4* xr = (const float4*)(xs + bb * 3000);
    float acc = b3[co];
    #pragma unroll 4
    for (int j4 = 0; j4 < 750; j4++) {
        float4 xv = xr[j4];
        int j = j4 * 4;
        acc += g_w3t[(j + 0) * C3 + co] * xv.x;
        acc += g_w3t[(j + 1) * C3 + co] * xv.y;
        acc += g_w3t[(j + 2) * C3 + co] * xv.z;
        acc += g_w3t[(j + 3) * C3 + co] * xv.w;
    }
    float v = tanhf(acc);
    int b = b0 + bb;
    out_h[b * C3 + co]   = v;
    g_final[b * C3 + co] = v;
}

// ---------------- row-normalize final -> bf16 hi/lo (padded K 100->128) ----------------
__global__ void k_norm() {
    int gw = (blockIdx.x * blockDim.x + threadIdx.x) >> 5;
    int lane = threadIdx.x & 31;
    if (gw >= BATCH) return;
    const float* f = g_final + gw * C3;
    float s = 0.f;
    for (int c = lane; c < C3; c += 32) { float v = f[c]; s += v * v; }
    #pragma unroll
    for (int o = 16; o; o >>= 1) s += __shfl_xor_sync(0xffffffffu, s, o);
    float n = sqrtf(s);
    __nv_bfloat16* oh = g_Fnh + gw * KPAD_F;
    __nv_bfloat16* ol = g_Fnl + gw * KPAD_F;
    for (int c = lane; c < C3; c += 32) {
        float v = f[c] / n;
        __nv_bfloat16 h = __float2bfloat16(v);
        oh[c] = h;
        ol[c] = __float2bfloat16(v - __bfloat162float(h));
    }
    for (int c = C3 + lane; c < KPAD_F; c += 32) {
        oh[c] = __float2bfloat16(0.f);
        ol[c] = __float2bfloat16(0.f);
    }
}

// ================= tensor-core symmetric Gram (split-bf16, 3-MMA) =================
// C = Xhi*Xhi^T + Xhi*Xlo^T + Xlo*Xhi^T ; 128x128 tiles, triu only, packed output.
#define GBM 128
#define GBK 32
#define GSTAGES 3
#define SMS 40                         // halves per smem row (32 data + 8 pad; 80B stride -> ldmatrix conflict-free)
#define MSZ (128*SMS)                  // halves per matrix tile
#define STG (4*MSZ)                    // halves per stage (Ahi,Alo,Bhi,Blo)

__device__ __forceinline__ void cp16(__nv_bfloat16* dst, const __nv_bfloat16* src) {
    unsigned a = (unsigned)__cvta_generic_to_shared(dst);
    asm volatile("cp.async.cg.shared.global [%0], [%1], 16;\n" :: "r"(a), "l"(src));
}

__device__ __forceinline__ void ldm4(unsigned* r, const __nv_bfloat16* p) {
    unsigned a = (unsigned)__cvta_generic_to_shared(p);
    asm volatile("ldmatrix.sync.aligned.m8n8.x4.shared.b16 {%0,%1,%2,%3}, [%4];\n"
                 : "=r"(r[0]), "=r"(r[1]), "=r"(r[2]), "=r"(r[3]) : "r"(a));
}

__device__ __forceinline__ void mma16816(float* d, const unsigned* a, const unsigned* b) {
    asm volatile("mma.sync.aligned.m16n8k16.row.col.f32.bf16.bf16.f32 "
                 "{%0,%1,%2,%3}, {%4,%5,%6,%7}, {%8,%9}, {%0,%1,%2,%3};\n"
                 : "+f"(d[0]), "+f"(d[1]), "+f"(d[2]), "+f"(d[3])
                 : "r"(a[0]), "r"(a[1]), "r"(a[2]), "r"(a[3]), "r"(b[0]), "r"(b[1]));
}

__device__ __forceinline__ void g_load_stage(__nv_bfloat16* dst,
        const __nv_bfloat16* Xhi, const __nv_bfloat16* Xlo,
        int i0, int j0, int kc, int ldk, int t) {
    #pragma unroll
    for (int q = 0; q < 2; q++) {
        int idx = t + q * 256;            // 0..511
        int row = idx >> 2, c = idx & 3;  // row 0..127, 16B chunk 0..3
        int so = row * SMS + c * 8;
        size_t goA = (size_t)(i0 + row) * ldk + kc + c * 8;
        size_t goB = (size_t)(j0 + row) * ldk + kc + c * 8;
        cp16(dst + 0 * MSZ + so, Xhi + goA);
        cp16(dst + 1 * MSZ + so, Xlo + goA);
        cp16(dst + 2 * MSZ + so, Xhi + goB);
        cp16(dst + 3 * MSZ + so, Xlo + goB);
    }
}

__global__ __launch_bounds__(256)
void k_gram_t(const __nv_bfloat16* __restrict__ Xhi, const __nv_bfloat16* __restrict__ Xlo,
              int ldk, int kIters, float* __restrict__ out) {
    extern __shared__ __nv_bfloat16 sm[];   // GSTAGES * STG halves

    // triangular tile map (32x32 tiles, tj >= ti)
    int p = blockIdx.x;
    int ti = 0, rem = 32;
    while (p >= rem) { p -= rem; rem--; ti++; }
    int tj = ti + p;
    const int i0 = ti * GBM, j0 = tj * GBM;

    int t = threadIdx.x;
    int lane = t & 31, wid = t >> 5;
    int wm = wid >> 2, wn = wid & 3;      // warp grid 2(M) x 4(N); warp tile 64x32

    float acc[4][4][4];
    #pragma unroll
    for (int mt = 0; mt < 4; mt++)
        #pragma unroll
        for (int nt = 0; nt < 4; nt++)
            #pragma unroll
            for (int e = 0; e < 4; e++) acc[mt][nt][e] = 0.f;

    // prologue
    #pragma unroll
    for (int s = 0; s < GSTAGES - 1; s++) {
        if (s < kIters) g_load_stage(sm + s * STG, Xhi, Xlo, i0, j0, s * GBK, ldk, t);
        asm volatile("cp.async.commit_group;\n");
    }

    int lr = lane & 15;
    int lc = (lane >> 4) << 3;

    for (int it = 0; it < kIters; it++) {
        asm volatile("cp.async.wait_group %0;\n" :: "n"(GSTAGES - 2));
        __syncthreads();

        int nxt = it + GSTAGES - 1;
        if (nxt < kIters) g_load_stage(sm + (nxt % GSTAGES) * STG, Xhi, Xlo, i0, j0, nxt * GBK, ldk, t);
        asm volatile("cp.async.commit_group;\n");

        const __nv_bfloat16* buf = sm + (it % GSTAGES) * STG;
        const __nv_bfloat16* sAh = buf;
        const __nv_bfloat16* sAl = buf + MSZ;
        const __nv_bfloat16* sBh = buf + 2 * MSZ;
        const __nv_bfloat16* sBl = buf + 3 * MSZ;

        #pragma unroll
        for (int ks = 0; ks < GBK; ks += 16) {
            unsigned ah[4][4], al[4][4], bh[4][2], bl[4][2];
            #pragma unroll
            for (int mt = 0; mt < 4; mt++) {
                ldm4(ah[mt], sAh + (wm * 64 + mt * 16 + lr) * SMS + ks + lc);
                ldm4(al[mt], sAl + (wm * 64 + mt * 16 + lr) * SMS + ks + lc);
            }
            #pragma unroll
            for (int bt = 0; bt < 2; bt++) {
                unsigned r4[4];
                ldm4(r4, sBh + (wn * 32 + bt * 16 + lr) * SMS + ks + lc);
                bh[2 * bt][0] = r4[0]; bh[2 * bt][1] = r4[2];
                bh[2 * bt + 1][0] = r4[1]; bh[2 * bt + 1][1] = r4[3];
                ldm4(r4, sBl + (wn * 32 + bt * 16 + lr) * SMS + ks + lc);
                bl[2 * bt][0] = r4[0]; bl[2 * bt][1] = r4[2];
                bl[2 * bt + 1][0] = r4[1]; bl[2 * bt + 1][1] = r4[3];
            }
            #pragma unroll
            for (int mt = 0; mt < 4; mt++)
                #pragma unroll
                for (int nt = 0; nt < 4; nt++) {
                    mma16816(acc[mt][nt], ah[mt], bh[nt]);
                    mma16816(acc[mt][nt], ah[mt], bl[nt]);
                    mma16816(acc[mt][nt], al[mt], bh[nt]);
                }
        }
        __syncthreads();
    }

    // epilogue: packed triu  idx(i,j) = i*(8191-i)/2 + (j-i-1)
    int r = lane >> 2, cp = (lane & 3) * 2;
    #pragma unroll
    for (int mt = 0; mt < 4; mt++) {
        #pragma unroll
        for (int h = 0; h < 2; h++) {
            int i = i0 + wm * 64 + mt * 16 + r + h * 8;
            int base = i * (8191 - i) / 2 - i - 1;
            #pragma unroll
            for (int nt = 0; nt < 4; nt++) {
                int j = j0 + wn * 32 + nt * 8 + cp;
                float v0 = acc[mt][nt][2 * h + 0];
                float v1 = acc[mt][nt][2 * h + 1];
                if (j > i)     out[base + j]     = v0;
                if (j + 1 > i) out[base + j + 1] = v1;
            }
        }
    }
}

// ---------------- launch ----------------
extern "C" void kernel_launch(void* const* d_in, const int* in_sizes, int n_in,
                              void* d_out, int out_size) {
    const int*   x   = (const int*)  d_in[0];
    const float* emb = (const float*)d_in[1];
    const float* w1  = (const float*)d_in[2];
    const float* b1  = (const float*)d_in[3];
    const float* w2  = (const float*)d_in[4];
    const float* b2  = (const float*)d_in[5];
    const float* w3  = (const float*)d_in[6];
    const float* b3  = (const float*)d_in[7];
    const float* g1  = (const float*)d_in[8];
    const float* be1 = (const float*)d_in[9];
    const float* g2  = (const float*)d_in[10];
    const float* be2 = (const float*)d_in[11];
    float* out = (float*)d_out;

    const int gramSmem = GSTAGES * STG * 2;   // bytes
    cudaFuncSetAttribute(k_conv1, cudaFuncAttributeMaxDynamicSharedMemorySize, 2 * 9600 * 4);
    cudaFuncSetAttribute(k_conv2, cudaFuncAttributeMaxDynamicSharedMemorySize, 4 * 4800 * 4);
    cudaFuncSetAttribute(k_gram_t, cudaFuncAttributeMaxDynamicSharedMemorySize, gramSmem);

    k_scales<<<(VOCAB * 32 + 255) / 256, 256>>>(emb);
    k_gather<<<BATCH, 256>>>(x, emb);
    k_transpose<<<(1650000 + 255) / 256, 256>>>(w1, w2, w3);

    // big input Gram on tensor cores (independent of convs; queue first)
    {
        __nv_bfloat16 *eh, *el;
        cudaGetSymbolAddress((void**)&eh, g_Ehi);
        cudaGetSymbolAddress((void**)&el, g_Elo);
        k_gram_t<<<528, 256, gramSmem>>>(eh, el, KPAD_E, KPAD_E / GBK, out + HOUT);
    }

    k_conv1<<<BATCH / 2, 320, 2 * 9600 * 4>>>(b1);
    k_bnstats<<<C1, 256>>>(1);
    k_bnapply<<<2048, 256>>>(g1, be1, 1);

    k_conv2<<<BATCH / 4, 608, 4 * 4800 * 4>>>(b2);
    k_bnstats<<<C2, 256>>>(2);
    k_bnapply<<<2048, 256>>>(g2, be2, 2);

    k_conv3<<<BATCH / 4, 512>>>(b3, out);
    k_norm<<<BATCH * 32 / 256, 256>>>();

    {
        __nv_bfloat16 *fh, *fl;
        cudaGetSymbolAddress((void**)&fh, g_Fnh);
        cudaGetSymbolAddress((void**)&fl, g_Fnl);
        k_gram_t<<<528, 256, gramSmem>>>(fh, fl, KPAD_F, KPAD_F / GBK, out + HOUT + NPAIRS);
    }
}